// round 1
// baseline (speedup 1.0000x reference)
#include <cuda_runtime.h>

#define NN    10000
#define NE    160000
#define H     64
#define T     12
#define TP    14
#define OUTC  12
#define NODE_F (H*T)   // 768

// ---------------- scratch (no allocations allowed) ----------------
__device__ float g_buf[2][NN * NODE_F];   // ping-pong feature buffers (2 x 30.7 MB)
__device__ int   g_counts[NN];
__device__ int   g_rowptr[NN + 1];
__device__ int   g_cursor[NN];
__device__ int   g_col[NE];
__device__ float g_wcsr[NE];
__device__ float g_deg[NN];
__device__ float g_dis[NN];

// ---------------- CSR build ----------------
__global__ void init_kernel() {
    int i = blockIdx.x * blockDim.x + threadIdx.x;
    if (i < NN) { g_counts[i] = 0; g_deg[i] = 1.0f; }  // self-loop weight 1
}

__global__ void count_kernel(const int* __restrict__ dst, const float* __restrict__ ew) {
    int e = blockIdx.x * blockDim.x + threadIdx.x;
    if (e < NE) {
        int d = dst[e];
        atomicAdd(&g_counts[d], 1);
        atomicAdd(&g_deg[d], ew[e]);
    }
}

__global__ void scan_kernel() {
    __shared__ int temp[1024];
    __shared__ int carry;
    int tid = threadIdx.x;
    if (tid == 0) carry = 0;
    __syncthreads();
    for (int base = 0; base < NN; base += 1024) {
        int i = base + tid;
        int v = (i < NN) ? g_counts[i] : 0;
        temp[tid] = v;
        __syncthreads();
        for (int off = 1; off < 1024; off <<= 1) {
            int t = (tid >= off) ? temp[tid - off] : 0;
            __syncthreads();
            temp[tid] += t;
            __syncthreads();
        }
        if (i < NN) {
            int excl = carry + temp[tid] - v;
            g_rowptr[i] = excl;
            g_cursor[i] = excl;
        }
        int tot = temp[1023];
        __syncthreads();
        if (tid == 0) carry += tot;
        __syncthreads();
    }
    if (tid == 0) g_rowptr[NN] = carry;
}

__global__ void dis_kernel() {
    int i = blockIdx.x * blockDim.x + threadIdx.x;
    if (i < NN) g_dis[i] = rsqrtf(g_deg[i]);   // deg >= 1 always
}

__global__ void fill_kernel(const int* __restrict__ src, const int* __restrict__ dst,
                            const float* __restrict__ ew) {
    int e = blockIdx.x * blockDim.x + threadIdx.x;
    if (e < NE) {
        int d = dst[e];
        int pos = atomicAdd(&g_cursor[d], 1);
        g_col[pos]  = src[e];
        g_wcsr[pos] = ew[e];
    }
}

// ---------------- gated temporal conv (fused gate) ----------------
// out[n,o,t] = (P+bP) * sigmoid(Q+bQ),  P/Q = conv1d over (CIN,3), pad 1.
// Block: 256 thr = 64 out-channels x 4 nodes. Weights staged transposed+padded
// in smem chunks so reads are conflict-free (lanes span consecutive o).
template <int CIN>
__global__ void __launch_bounds__(256) tconv_gated(
        const float* __restrict__ ext_x, int si, int di,
        const float* __restrict__ w, const float* __restrict__ b) {
    const int NB  = 4;
    const int CCH = 16;   // channel chunk
    const int WP  = 130;  // padded pitch for 128 pre-gate channels
    __shared__ float xs[NB * CIN * TP];
    __shared__ float ws[CCH * 3 * WP];

    const float* xin = (si < 0) ? ext_x : g_buf[si];
    float* out = g_buf[di];
    int node0 = blockIdx.x * NB;
    int tid = threadIdx.x;

    // load inputs (zero-padded in time)
    for (int i = tid; i < NB * CIN * T; i += 256) {
        int nn = i / (CIN * T); int r = i % (CIN * T);
        int c = r / T; int t = r % T;
        xs[(nn * CIN + c) * TP + t + 1] = xin[(size_t)(node0 + nn) * CIN * T + r];
    }
    for (int i = tid; i < NB * CIN; i += 256) {
        xs[i * TP] = 0.f;
        xs[i * TP + TP - 1] = 0.f;
    }

    int o  = tid & 63;
    int nn = tid >> 6;
    float accP[T], accQ[T];
#pragma unroll
    for (int t = 0; t < T; t++) { accP[t] = 0.f; accQ[t] = 0.f; }

    for (int c0 = 0; c0 < CIN; c0 += CCH) {
        __syncthreads();   // guards xs on first iter, ws reuse afterwards
        // stage weight chunk: ws[(cl*3+k)*WP + oo] = w[oo][c0+cl][k]
        for (int i = tid; i < 128 * CCH * 3; i += 256) {
            int oo = i / (CCH * 3); int j = i % (CCH * 3);
            ws[j * WP + oo] = w[(size_t)oo * (CIN * 3) + c0 * 3 + j];
        }
        __syncthreads();
        const float* xb = &xs[(nn * CIN + c0) * TP];
#pragma unroll 2
        for (int cl = 0; cl < CCH; cl++) {
            float xv[TP];
#pragma unroll
            for (int t = 0; t < TP; t++) xv[t] = xb[cl * TP + t];
#pragma unroll
            for (int k = 0; k < 3; k++) {
                float wp = ws[(cl * 3 + k) * WP + o];
                float wq = ws[(cl * 3 + k) * WP + o + 64];
#pragma unroll
                for (int t = 0; t < T; t++) {
                    accP[t] = fmaf(wp, xv[t + k], accP[t]);
                    accQ[t] = fmaf(wq, xv[t + k], accQ[t]);
                }
            }
        }
    }
    float bp = b[o], bq = b[o + 64];
    float* op = out + (size_t)(node0 + nn) * NODE_F + o * T;
#pragma unroll
    for (int t = 0; t < T; t++) {
        float q = accQ[t] + bq;
        op[t] = (accP[t] + bp) / (1.f + __expf(-q));
    }
}

// ---------------- GCN per-node channel transform: xt = W @ x ----------------
// Block: 256 thr = 32 o-pairs x 8 nodes; each thread owns channels o and o+32.
__global__ void __launch_bounds__(256) gcn_transform(int si, int di,
                                                     const float* __restrict__ W) {
    const int NB = 8;
    __shared__ float xs[NB * NODE_F];
    __shared__ float wT[64 * 65];
    const float* xin = g_buf[si];
    float* out = g_buf[di];
    int node0 = blockIdx.x * NB;
    int tid = threadIdx.x;

    for (int i = tid; i < 64 * 64; i += 256) {
        int o = i >> 6, c = i & 63;
        wT[c * 65 + o] = W[i];
    }
    for (int i = tid; i < NB * NODE_F; i += 256)
        xs[i] = xin[(size_t)node0 * NODE_F + i];
    __syncthreads();

    int o  = tid & 31;
    int nn = tid >> 5;
    float acc0[T], acc1[T];
#pragma unroll
    for (int t = 0; t < T; t++) { acc0[t] = 0.f; acc1[t] = 0.f; }
    const float* xb = &xs[nn * NODE_F];
#pragma unroll 4
    for (int c = 0; c < 64; c++) {
        float w0 = wT[c * 65 + o];
        float w1 = wT[c * 65 + o + 32];
#pragma unroll
        for (int t = 0; t < T; t++) {
            float xv = xb[c * T + t];
            acc0[t] = fmaf(w0, xv, acc0[t]);
            acc1[t] = fmaf(w1, xv, acc1[t]);
        }
    }
    float* op = out + (size_t)(node0 + nn) * NODE_F;
#pragma unroll
    for (int t = 0; t < T; t++) {
        op[o * T + t]        = acc0[t];
        op[(o + 32) * T + t] = acc1[t];
    }
}

// ---------------- GCN aggregation (+bias, relu) via CSR gather ----------------
// Block per dst node; 256 threads x 3 features each. Reads hit L2 (buffer is
// L2-resident). No atomics.
__global__ void __launch_bounds__(256) gcn_aggregate(int si, int di,
                                                     const float* __restrict__ bias) {
    const float* xt = g_buf[si];
    float* out = g_buf[di];
    int n = blockIdx.x;
    int tid = threadIdx.x;
    float dn = g_dis[n];
    float self = dn * dn;
    const float* xn = xt + (size_t)n * NODE_F;
    float acc[3];
#pragma unroll
    for (int r = 0; r < 3; r++) acc[r] = self * xn[tid + 256 * r];
    int e0 = g_rowptr[n], e1 = g_rowptr[n + 1];
    for (int e = e0; e < e1; e++) {
        int s = g_col[e];
        float nrm = dn * g_wcsr[e] * g_dis[s];
        const float* xsp = xt + (size_t)s * NODE_F;
#pragma unroll
        for (int r = 0; r < 3; r++) acc[r] = fmaf(nrm, xsp[tid + 256 * r], acc[r]);
    }
#pragma unroll
    for (int r = 0; r < 3; r++) {
        int j = tid + 256 * r;
        float v = acc[r] + bias[j / T];
        out[(size_t)n * NODE_F + j] = fmaxf(v, 0.f);
    }
}

// ---------------- final conv (collapses T), writes d_out (1,N,12) ----------------
__global__ void __launch_bounds__(256) final_conv(int si, const float* __restrict__ w,
                                                  const float* __restrict__ b,
                                                  float* __restrict__ out) {
    const float* xin = g_buf[si];
    int gw   = (blockIdx.x * blockDim.x + threadIdx.x) >> 5;
    int lane = threadIdx.x & 31;
    if (gw >= NN) return;
    float acc[OUTC];
#pragma unroll
    for (int o = 0; o < OUTC; o++) acc[o] = 0.f;
    const float* xp = xin + (size_t)gw * NODE_F;
    for (int j = lane; j < NODE_F; j += 32) {
        float xv = xp[j];
#pragma unroll
        for (int o = 0; o < OUTC; o++)
            acc[o] = fmaf(__ldg(&w[o * NODE_F + j]), xv, acc[o]);
    }
#pragma unroll
    for (int o = 0; o < OUTC; o++) {
        float v = acc[o];
#pragma unroll
        for (int off = 16; off; off >>= 1) v += __shfl_xor_sync(0xffffffffu, v, off);
        if (lane == 0) out[(size_t)gw * OUTC + o] = v + b[o];
    }
}

// ---------------- launch ----------------
extern "C" void kernel_launch(void* const* d_in, const int* in_sizes, int n_in,
                              void* d_out, int out_size) {
    const float* x      = (const float*)d_in[0];
    const int*   ei     = (const int*)  d_in[1];
    const float* ew     = (const float*)d_in[2];
    const float* tc1a_w = (const float*)d_in[3];
    const float* tc1a_b = (const float*)d_in[4];
    const float* gc1_w  = (const float*)d_in[5];
    const float* gc1_b  = (const float*)d_in[6];
    const float* tc1b_w = (const float*)d_in[7];
    const float* tc1b_b = (const float*)d_in[8];
    const float* tc2a_w = (const float*)d_in[9];
    const float* tc2a_b = (const float*)d_in[10];
    const float* gc2_w  = (const float*)d_in[11];
    const float* gc2_b  = (const float*)d_in[12];
    const float* tc2b_w = (const float*)d_in[13];
    const float* tc2b_b = (const float*)d_in[14];
    const float* fin_w  = (const float*)d_in[15];
    const float* fin_b  = (const float*)d_in[16];
    float* out = (float*)d_out;

    const int* src = ei;
    const int* dst = ei + NE;

    // CSR build (per launch; deterministic up to fp-add order in deg)
    init_kernel<<<(NN + 255) / 256, 256>>>();
    count_kernel<<<(NE + 255) / 256, 256>>>(dst, ew);
    scan_kernel<<<1, 1024>>>();
    fill_kernel<<<(NE + 255) / 256, 256>>>(src, dst, ew);
    dis_kernel<<<(NN + 255) / 256, 256>>>();

    // pipeline (ping-pong between g_buf[0] / g_buf[1])
    tconv_gated<32><<<NN / 4, 256>>>(x, -1, 0, tc1a_w, tc1a_b);
    gcn_transform  <<<NN / 8, 256>>>(0, 1, gc1_w);
    gcn_aggregate  <<<NN,     256>>>(1, 0, gc1_b);
    tconv_gated<64><<<NN / 4, 256>>>(nullptr, 0, 1, tc1b_w, tc1b_b);
    tconv_gated<64><<<NN / 4, 256>>>(nullptr, 1, 0, tc2a_w, tc2a_b);
    gcn_transform  <<<NN / 8, 256>>>(0, 1, gc2_w);
    gcn_aggregate  <<<NN,     256>>>(1, 0, gc2_b);
    tconv_gated<64><<<NN / 4, 256>>>(nullptr, 0, 1, tc2b_w, tc2b_b);
    final_conv     <<<NN * 32 / 256, 256>>>(1, fin_w, fin_b, out);
}

// round 3
// speedup vs baseline: 1.0408x; 1.0408x over previous
#include <cuda_runtime.h>

#define NN    10000
#define NE    160000
#define H     64
#define T     12
#define TP    14
#define OUTC  12
#define NODE_F (H*T)   // 768

typedef unsigned long long u64;

// ---------------- packed f32x2 helpers (sm_100+) ----------------
__device__ __forceinline__ u64 pk2(float lo, float hi) {
    u64 r; asm("mov.b64 %0,{%1,%2};" : "=l"(r) : "f"(lo), "f"(hi)); return r;
}
__device__ __forceinline__ void upk2(u64 v, float& lo, float& hi) {
    asm("mov.b64 {%0,%1},%2;" : "=f"(lo), "=f"(hi) : "l"(v));
}
__device__ __forceinline__ void fma2(u64& d, u64 a, u64 b) {
    asm("fma.rn.f32x2 %0,%1,%2,%0;" : "+l"(d) : "l"(a), "l"(b));
}

// ---------------- scratch (no allocations allowed) ----------------
__device__ float g_buf[2][NN * NODE_F];   // ping-pong feature buffers (2 x 30.7 MB)
__device__ int   g_counts[NN];
__device__ int   g_rowptr[NN + 1];
__device__ int   g_cursor[NN];
__device__ int   g_col[NE];
__device__ int   g_dstE[NE];
__device__ float g_wcsr[NE];
__device__ float g_deg[NN];
__device__ float g_dis[NN];

// ---------------- CSR build ----------------
__global__ void init_kernel() {
    int i = blockIdx.x * blockDim.x + threadIdx.x;
    if (i < NN) { g_counts[i] = 0; g_deg[i] = 1.0f; }  // self-loop weight 1
}

__global__ void count_kernel(const int* __restrict__ dst, const float* __restrict__ ew) {
    int e = blockIdx.x * blockDim.x + threadIdx.x;
    if (e < NE) {
        int d = dst[e];
        atomicAdd(&g_counts[d], 1);
        atomicAdd(&g_deg[d], ew[e]);
    }
}

__global__ void scan_kernel() {
    __shared__ int temp[1024];
    __shared__ int carry;
    int tid = threadIdx.x;
    if (tid == 0) carry = 0;
    __syncthreads();
    for (int base = 0; base < NN; base += 1024) {
        int i = base + tid;
        int v = (i < NN) ? g_counts[i] : 0;
        temp[tid] = v;
        __syncthreads();
        for (int off = 1; off < 1024; off <<= 1) {
            int t = (tid >= off) ? temp[tid - off] : 0;
            __syncthreads();
            temp[tid] += t;
            __syncthreads();
        }
        if (i < NN) {
            int excl = carry + temp[tid] - v;
            g_rowptr[i] = excl;
            g_cursor[i] = excl;
        }
        int tot = temp[1023];
        __syncthreads();
        if (tid == 0) carry += tot;
        __syncthreads();
    }
    if (tid == 0) g_rowptr[NN] = carry;
}

__global__ void dis_kernel() {
    int i = blockIdx.x * blockDim.x + threadIdx.x;
    if (i < NN) g_dis[i] = rsqrtf(g_deg[i]);   // deg >= 1 always
}

__global__ void fill_kernel(const int* __restrict__ src, const int* __restrict__ dst,
                            const float* __restrict__ ew) {
    int e = blockIdx.x * blockDim.x + threadIdx.x;
    if (e < NE) {
        int d = dst[e];
        int pos = atomicAdd(&g_cursor[d], 1);
        g_col[pos]  = src[e];
        g_dstE[pos] = d;
        g_wcsr[pos] = ew[e];
    }
}

// fold full normalization coefficient into the edge weight:
// nrm = dis[dst] * ew * dis[src]
__global__ void norm_kernel() {
    int e = blockIdx.x * blockDim.x + threadIdx.x;
    if (e < NE)
        g_wcsr[e] = g_wcsr[e] * g_dis[g_dstE[e]] * g_dis[g_col[e]];
}

// ---------------- gated temporal conv (fused gate, f32x2 packed) ----------------
// out[n,o,t] = (P+bP) * sigmoid(Q+bQ),  P/Q = conv1d over (CIN,3), pad 1.
// Block: 256 thr = 64 out-channels x 4 nodes. Weights staged transposed+padded
// in smem so per-o reads are conflict-free broadcasts.
template <int CIN>
__global__ void __launch_bounds__(256) tconv_gated(
        const float* __restrict__ ext_x, int si, int di,
        const float* __restrict__ w, const float* __restrict__ b) {
    const int NB  = 4;
    const int CCH = 16;   // channel chunk
    const int WP  = 130;  // padded pitch for 128 pre-gate channels
    __shared__ float xs[NB * CIN * TP];
    __shared__ float ws[CCH * 3 * WP];

    const float* xin = (si < 0) ? ext_x : g_buf[si];
    float* out = g_buf[di];
    int node0 = blockIdx.x * NB;
    int tid = threadIdx.x;

    // load inputs (zero-padded in time)
    for (int i = tid; i < NB * CIN * T; i += 256) {
        int nn = i / (CIN * T); int r = i % (CIN * T);
        int c = r / T; int t = r % T;
        xs[(nn * CIN + c) * TP + t + 1] = xin[(size_t)(node0 + nn) * CIN * T + r];
    }
    for (int i = tid; i < NB * CIN; i += 256) {
        xs[i * TP] = 0.f;
        xs[i * TP + TP - 1] = 0.f;
    }

    int o  = tid & 63;
    int nn = tid >> 6;
    u64 accP[6], accQ[6];
#pragma unroll
    for (int i = 0; i < 6; i++) { accP[i] = 0ull; accQ[i] = 0ull; }

    for (int c0 = 0; c0 < CIN; c0 += CCH) {
        __syncthreads();   // guards xs on first iter, ws reuse afterwards
        // stage weight chunk: ws[(cl*3+k)*WP + oo] = w[oo][c0+cl][k]
        for (int i = tid; i < 128 * CCH * 3; i += 256) {
            int oo = i / (CCH * 3); int j = i % (CCH * 3);
            ws[j * WP + oo] = w[(size_t)oo * (CIN * 3) + c0 * 3 + j];
        }
        __syncthreads();
        const float* xb = &xs[(nn * CIN + c0) * TP];
#pragma unroll 2
        for (int cl = 0; cl < CCH; cl++) {
            // xb row is 8B-aligned (TP*4 = 56 bytes, base offsets even floats)
            float2 pe[7];
            const float2* xr = reinterpret_cast<const float2*>(xb + cl * TP);
#pragma unroll
            for (int i = 0; i < 7; i++) pe[i] = xr[i];
            u64 peU[7], po[6];
#pragma unroll
            for (int i = 0; i < 7; i++) peU[i] = pk2(pe[i].x, pe[i].y);
#pragma unroll
            for (int i = 0; i < 6; i++) po[i] = pk2(pe[i].y, pe[i + 1].x);
#pragma unroll
            for (int k = 0; k < 3; k++) {
                float wp = ws[(cl * 3 + k) * WP + o];
                float wq = ws[(cl * 3 + k) * WP + o + 64];
                u64 wpp = pk2(wp, wp);
                u64 wqq = pk2(wq, wq);
#pragma unroll
                for (int i = 0; i < 6; i++) {
                    u64 xp = (k == 0) ? peU[i] : (k == 1) ? po[i] : peU[i + 1];
                    fma2(accP[i], wpp, xp);
                    fma2(accQ[i], wqq, xp);
                }
            }
        }
    }
    float bp = b[o], bq = b[o + 64];
    float* op = out + (size_t)(node0 + nn) * NODE_F + o * T;
#pragma unroll
    for (int i = 0; i < 6; i++) {
        float p0, p1, q0, q1;
        upk2(accP[i], p0, p1);
        upk2(accQ[i], q0, q1);
        float v0 = (p0 + bp) / (1.f + __expf(-(q0 + bq)));
        float v1 = (p1 + bp) / (1.f + __expf(-(q1 + bq)));
        op[2 * i]     = v0;
        op[2 * i + 1] = v1;
    }
}

// ---------------- GCN per-node channel transform: xt = W @ x (f32x2) ----------------
// Block: 256 thr = 32 o-pairs x 8 nodes; each thread owns channels o and o+32.
__global__ void __launch_bounds__(256) gcn_transform(int si, int di,
                                                     const float* __restrict__ W) {
    const int NB = 8;
    __shared__ float xs[NB * NODE_F];
    __shared__ float wT[64 * 65];
    const float* xin = g_buf[si];
    float* out = g_buf[di];
    int node0 = blockIdx.x * NB;
    int tid = threadIdx.x;

    for (int i = tid; i < 64 * 64; i += 256) {
        int o = i >> 6, c = i & 63;
        wT[c * 65 + o] = W[i];
    }
    for (int i = tid; i < NB * NODE_F; i += 256)
        xs[i] = xin[(size_t)node0 * NODE_F + i];
    __syncthreads();

    int o  = tid & 31;
    int nn = tid >> 5;
    u64 acc0[6], acc1[6];
#pragma unroll
    for (int i = 0; i < 6; i++) { acc0[i] = 0ull; acc1[i] = 0ull; }
    const float* xb = &xs[nn * NODE_F];
#pragma unroll 4
    for (int c = 0; c < 64; c++) {
        // 12 floats per channel, 8B-aligned -> 6 packed loads
        const u64* xr = reinterpret_cast<const u64*>(xb + c * T);
        float w0 = wT[c * 65 + o];
        float w1 = wT[c * 65 + o + 32];
        u64 w00 = pk2(w0, w0);
        u64 w11 = pk2(w1, w1);
#pragma unroll
        for (int i = 0; i < 6; i++) {
            u64 xv = xr[i];
            fma2(acc0[i], w00, xv);
            fma2(acc1[i], w11, xv);
        }
    }
    u64* op = reinterpret_cast<u64*>(out + (size_t)(node0 + nn) * NODE_F);
#pragma unroll
    for (int i = 0; i < 6; i++) {
        op[o * 6 + i]        = acc0[i];
        op[(o + 32) * 6 + i] = acc1[i];
    }
}

// ---------------- GCN aggregation (+bias, relu) via CSR gather ----------------
// Block per dst node; 256 threads x 3 features each. Edge coefficient fully
// precomputed (norm_kernel) so the loop is pure gather+FMA out of L2.
__global__ void __launch_bounds__(256) gcn_aggregate(int si, int di,
                                                     const float* __restrict__ bias) {
    const float* xt = g_buf[si];
    float* out = g_buf[di];
    int n = blockIdx.x;
    int tid = threadIdx.x;
    float dn = g_dis[n];
    float self = dn * dn;
    const float* xn = xt + (size_t)n * NODE_F;
    float acc[3];
#pragma unroll
    for (int r = 0; r < 3; r++) acc[r] = self * xn[tid + 256 * r];
    int e0 = g_rowptr[n], e1 = g_rowptr[n + 1];
#pragma unroll 2
    for (int e = e0; e < e1; e++) {
        int s = g_col[e];
        float nrm = g_wcsr[e];
        const float* xsp = xt + (size_t)s * NODE_F;
#pragma unroll
        for (int r = 0; r < 3; r++) acc[r] = fmaf(nrm, xsp[tid + 256 * r], acc[r]);
    }
#pragma unroll
    for (int r = 0; r < 3; r++) {
        int j = tid + 256 * r;
        float v = acc[r] + bias[j / T];
        out[(size_t)n * NODE_F + j] = fmaxf(v, 0.f);
    }
}

// ---------------- final conv (collapses T), writes d_out (1,N,12) ----------------
__global__ void __launch_bounds__(256) final_conv(int si, const float* __restrict__ w,
                                                  const float* __restrict__ b,
                                                  float* __restrict__ out) {
    const float* xin = g_buf[si];
    int gw   = (blockIdx.x * blockDim.x + threadIdx.x) >> 5;
    int lane = threadIdx.x & 31;
    if (gw >= NN) return;
    float acc[OUTC];
#pragma unroll
    for (int o = 0; o < OUTC; o++) acc[o] = 0.f;
    const float* xp = xin + (size_t)gw * NODE_F;
    for (int j = lane; j < NODE_F; j += 32) {
        float xv = xp[j];
#pragma unroll
        for (int o = 0; o < OUTC; o++)
            acc[o] = fmaf(__ldg(&w[o * NODE_F + j]), xv, acc[o]);
    }
#pragma unroll
    for (int o = 0; o < OUTC; o++) {
        float v = acc[o];
#pragma unroll
        for (int off = 16; off; off >>= 1) v += __shfl_xor_sync(0xffffffffu, v, off);
        if (lane == 0) out[(size_t)gw * OUTC + o] = v + b[o];
    }
}

// ---------------- launch ----------------
extern "C" void kernel_launch(void* const* d_in, const int* in_sizes, int n_in,
                              void* d_out, int out_size) {
    const float* x      = (const float*)d_in[0];
    const int*   ei     = (const int*)  d_in[1];
    const float* ew     = (const float*)d_in[2];
    const float* tc1a_w = (const float*)d_in[3];
    const float* tc1a_b = (const float*)d_in[4];
    const float* gc1_w  = (const float*)d_in[5];
    const float* gc1_b  = (const float*)d_in[6];
    const float* tc1b_w = (const float*)d_in[7];
    const float* tc1b_b = (const float*)d_in[8];
    const float* tc2a_w = (const float*)d_in[9];
    const float* tc2a_b = (const float*)d_in[10];
    const float* gc2_w  = (const float*)d_in[11];
    const float* gc2_b  = (const float*)d_in[12];
    const float* tc2b_w = (const float*)d_in[13];
    const float* tc2b_b = (const float*)d_in[14];
    const float* fin_w  = (const float*)d_in[15];
    const float* fin_b  = (const float*)d_in[16];
    float* out = (float*)d_out;

    const int* src = ei;
    const int* dst = ei + NE;

    // CSR build (per launch; deterministic up to fp-add order in deg)
    init_kernel<<<(NN + 255) / 256, 256>>>();
    count_kernel<<<(NE + 255) / 256, 256>>>(dst, ew);
    scan_kernel<<<1, 1024>>>();
    fill_kernel<<<(NE + 255) / 256, 256>>>(src, dst, ew);
    dis_kernel<<<(NN + 255) / 256, 256>>>();
    norm_kernel<<<(NE + 255) / 256, 256>>>();

    // pipeline (ping-pong between g_buf[0] / g_buf[1])
    tconv_gated<32><<<NN / 4, 256>>>(x, -1, 0, tc1a_w, tc1a_b);
    gcn_transform  <<<NN / 8, 256>>>(0, 1, gc1_w);
    gcn_aggregate  <<<NN,     256>>>(1, 0, gc1_b);
    tconv_gated<64><<<NN / 4, 256>>>(nullptr, 0, 1, tc1b_w, tc1b_b);
    tconv_gated<64><<<NN / 4, 256>>>(nullptr, 1, 0, tc2a_w, tc2a_b);
    gcn_transform  <<<NN / 8, 256>>>(0, 1, gc2_w);
    gcn_aggregate  <<<NN,     256>>>(1, 0, gc2_b);
    tconv_gated<64><<<NN / 4, 256>>>(nullptr, 0, 1, tc2b_w, tc2b_b);
    final_conv     <<<NN * 32 / 256, 256>>>(1, fin_w, fin_b, out);
}